// round 6
// baseline (speedup 1.0000x reference)
#include <cuda_runtime.h>
#include <cuda_bf16.h>

#define T_STEPS 100
#define BATCH   2048
#define NH      128
#define NORD    6
#define NSP     512

typedef unsigned long long ull;
typedef unsigned int u32;

// Scratch (device globals — no allocations allowed)
__device__ __align__(16) __nv_bfloat162 g_Hp[(size_t)T_STEPS * BATCH * NH]; // (hi,lo) per h elem
__device__ __align__(16) float g_h0[BATCH * NH];
__device__ __align__(16) float g_m0[BATCH * NORD];
__device__ __align__(16) __nv_bfloat162 g_Wcp[NSP * NH];                    // combined W, (hi,lo)
__device__ __align__(16) float g_bc[NSP];

__device__ __forceinline__ void ffma2(ull &d, ull a, ull b) {
    asm("fma.rn.f32x2 %0, %1, %2, %0;" : "+l"(d) : "l"(a), "l"(b));
}
__device__ __forceinline__ float sum2(ull a) {
    float lo, hi;
    asm("mov.b64 {%0,%1}, %2;" : "=f"(lo), "=f"(hi) : "l"(a));
    return lo + hi;
}
__device__ __forceinline__ u32 smem_u32(const void* p) {
    u32 a;
    asm("{ .reg .u64 t; cvta.to.shared.u64 t, %1; cvt.u32.u64 %0, t; }" : "=r"(a) : "l"(p));
    return a;
}
__device__ __forceinline__ __nv_bfloat162 split_bf(float x) {
    __nv_bfloat16 hi = __float2bfloat16(x);
    __nv_bfloat16 lo = __float2bfloat16(x - __bfloat162float(hi));
    __nv_bfloat162 r; r.x = hi; r.y = lo; return r;
}

// ---------------------------------------------------------------------------
// Kernel 1: initial states  m0 = ssp @ w_c^T,  h0 = ssp @ w_h^T
// ---------------------------------------------------------------------------
__global__ void k_setup(const float* __restrict__ ssp,
                        const float* __restrict__ w_c,
                        const float* __restrict__ w_h) {
    __shared__ float s[16 * 512];
    const int tid = threadIdx.x;
    const int b0 = blockIdx.x * 16;
    for (int i = tid; i < 16 * 512; i += 128) s[i] = ssp[(size_t)b0 * 512 + i];
    __syncthreads();
    {
        float acc[16];
        #pragma unroll
        for (int r = 0; r < 16; r++) acc[r] = 0.f;
        const float* wr = w_h + tid * 512;
        for (int k = 0; k < 512; k += 4) {
            const float4 w4 = *(const float4*)(wr + k);
            #pragma unroll
            for (int r = 0; r < 16; r++) {
                const float4 x4 = *(const float4*)(s + r * 512 + k);
                acc[r] += x4.x * w4.x + x4.y * w4.y + x4.z * w4.z + x4.w * w4.w;
            }
        }
        #pragma unroll
        for (int r = 0; r < 16; r++) g_h0[(size_t)(b0 + r) * NH + tid] = acc[r];
    }
    if (tid < 96) {
        const int o = tid >> 4, r = tid & 15;
        const float* wc = w_c + o * 512;
        float a = 0.f;
        for (int k = 0; k < 512; k++) a += s[r * 512 + k] * wc[k];
        g_m0[(size_t)(b0 + r) * NORD + o] = a;
    }
}

// ---------------------------------------------------------------------------
// Kernel 2: combined weights  Wc = W_ssp @ W_lin (stored split-bf16), bc
// ---------------------------------------------------------------------------
__global__ void k_combine(const float* __restrict__ W_lin,
                          const float* __restrict__ b_lin,
                          const float* __restrict__ W_ssp,
                          const float* __restrict__ b_ssp) {
    __shared__ float s[4 * 512];
    const int tid = threadIdx.x;
    const int i0 = blockIdx.x * 4;
    for (int i = tid; i < 4 * 512; i += 128) s[i] = W_ssp[(size_t)i0 * 512 + i];
    __syncthreads();

    float acc[4] = {0.f, 0.f, 0.f, 0.f};
    for (int j = 0; j < 512; j++) {
        const float wl = W_lin[j * 128 + tid];
        #pragma unroll
        for (int r = 0; r < 4; r++) acc[r] += s[r * 512 + j] * wl;
    }
    #pragma unroll
    for (int r = 0; r < 4; r++) g_Wcp[(size_t)(i0 + r) * NH + tid] = split_bf(acc[r]);

    if (tid < 4) {
        float a = b_ssp[i0 + tid];
        for (int j = 0; j < 512; j++) a += s[tid * 512 + j] * b_lin[j];
        g_bc[i0 + tid] = a;
    }
}

// ---------------------------------------------------------------------------
// Kernel 3: recurrence v3. 128 CTAs x 512 threads (16 warps, 4/SMSP), 16 rows.
// Warp w owns j-chunk [8w, 8w+8); lane = (row-group rh=lane>>3, j=lane&7);
// each lane accumulates rows {rh, rh+4, rh+8, rh+12} x 1 col.
// Extended K: x=[h(128), m'(6), v(2)], 34 k4 groups. Double-buffered x,
// stride 148 floats (row offsets {0,20,8,28} mod 32 banks -> conflict-free).
// ---------------------------------------------------------------------------
#define XS 148
__global__ void __launch_bounds__(512) k_recur(
    const float* __restrict__ vel,
    const float* __restrict__ ie_g, const float* __restrict__ he_g,
    const float* __restrict__ me_g, const float* __restrict__ ik_g,
    const float* __restrict__ hk_g, const float* __restrict__ mk_g,
    const float* __restrict__ AT_g, const float* __restrict__ BT_g) {
    extern __shared__ float sm[];
    float* s_wp = sm;                       // [34][128][4]   17408
    float* s_x  = sm + 17408;               // [2][16][148]    4736
    float* s_v  = sm + 17408 + 4736;        // [100][16][2]    3200
    float* s_m  = s_v + 3200;               // [16][8]          128
    float* s_he = s_m + 128;                // [128]
    float* s_c  = s_he + 128;               // AT[36] BT[6] me[6] ie[2]

    const int tid = threadIdx.x;
    const int b0 = blockIdx.x * 16;

    // Extended weight fill: W'[j] = [HK[j][0:128], MK[j][0:6], IK[j][0:2]]
    for (int idx = tid; idx < 34 * 128; idx += 512) {
        const int k4 = idx >> 7, j = idx & 127;
        float p0, p1, p2, p3;
        if (k4 < 32) {
            const float4 h4 = *(const float4*)(hk_g + j * 128 + k4 * 4);
            p0 = h4.x; p1 = h4.y; p2 = h4.z; p3 = h4.w;
        } else if (k4 == 32) {
            p0 = mk_g[j * 6 + 0]; p1 = mk_g[j * 6 + 1];
            p2 = mk_g[j * 6 + 2]; p3 = mk_g[j * 6 + 3];
        } else {
            p0 = mk_g[j * 6 + 4]; p1 = mk_g[j * 6 + 5];
            p2 = ik_g[j * 2 + 0]; p3 = ik_g[j * 2 + 1];
        }
        float4* d = (float4*)(s_wp + (size_t)idx * 4);
        *d = make_float4(p0, p1, p2, p3);
    }
    for (int idx = tid; idx < 16 * 128; idx += 512) {
        const int r = idx >> 7, j = idx & 127;
        s_x[r * XS + j] = g_h0[(size_t)(b0 + r) * NH + j];
    }
    for (int idx = tid; idx < 3200; idx += 512)
        s_v[idx] = vel[(size_t)(idx >> 5) * (BATCH * 2) + b0 * 2 + (idx & 31)];
    for (int idx = tid; idx < 96; idx += 512)
        s_m[(idx / 6) * 8 + (idx % 6)] = g_m0[(size_t)b0 * NORD + idx];
    if (tid < 128) s_he[tid] = he_g[tid];
    if (tid < 36) s_c[tid] = AT_g[tid];
    if (tid < 6) { s_c[36 + tid] = BT_g[tid]; s_c[42 + tid] = me_g[tid]; }
    if (tid < 2) s_c[48 + tid] = ie_g[tid];
    __syncthreads();

    const int lane = tid & 31;
    const int w = tid >> 5;               // warp = u/m row owner
    const int jj = w * 8 + (lane & 7);    // matvec output column
    const int rh = lane >> 3;             // row group (0..3)

    float he4[4];
    #pragma unroll
    for (int q = 0; q < 4; q++) he4[q] = s_he[lane + 32 * q];
    const float ie0 = s_c[48], ie1 = s_c[49];
    float at_row[6], bt_l = 0.f;
    #pragma unroll
    for (int k = 0; k < 6; k++) at_row[k] = (lane < 6) ? s_c[lane * 6 + k] : 0.f;
    if (lane < 6) bt_l = s_c[36 + lane];
    float me6[6];
    #pragma unroll
    for (int o = 0; o < 6; o++) me6[o] = s_c[42 + o];

    #pragma unroll 1
    for (int t = 0; t < T_STEPS; t++) {
        float* xr = s_x + (t & 1) * (16 * XS);
        float* xw = s_x + ((t & 1) ^ 1) * (16 * XS);

        // ---- Phase A: u for row w (old h from xr, old m from s_m) ----
        const float v0 = s_v[t * 32 + w * 2], v1 = s_v[t * 32 + w * 2 + 1];
        float u = 0.f;
        #pragma unroll
        for (int q = 0; q < 4; q++) u += he4[q] * xr[w * XS + lane + 32 * q];
        #pragma unroll
        for (int o = 16; o > 0; o >>= 1) u += __shfl_xor_sync(0xffffffffu, u, o);
        u += ie0 * v0 + ie1 * v1;
        #pragma unroll
        for (int o = 0; o < 6; o++) u += me6[o] * s_m[w * 8 + o];

        // ---- Phase B: m' = m + AT@m + BT*u ; stage m', v into xr row w ----
        float ma = 0.f;
        if (lane < 6) {
            ma = s_m[w * 8 + lane] + bt_l * u;
            #pragma unroll
            for (int k = 0; k < 6; k++) ma += at_row[k] * s_m[w * 8 + k];
        }
        __syncwarp();
        if (lane < 6) {
            s_m[w * 8 + lane] = ma;
            xr[w * XS + 128 + lane] = ma;
        }
        if (lane == 6) {
            xr[w * XS + 134] = v0;
            xr[w * XS + 135] = v1;
        }
        __syncthreads();

        // ---- Phase C: extended matvec, 4 rows x 1 col per lane ----
        ull acc[4];
        #pragma unroll
        for (int i = 0; i < 4; i++) acc[i] = 0ull;

        #pragma unroll 2
        for (int k4 = 0; k4 < 34; k4++) {
            const ulonglong2 wp = *(const ulonglong2*)(s_wp + ((size_t)k4 * 128 + jj) * 4);
            #pragma unroll
            for (int i = 0; i < 4; i++) {
                const ulonglong2 hp = *(const ulonglong2*)(xr + (4 * i + rh) * XS + k4 * 4);
                ffma2(acc[i], hp.x, wp.x);
                ffma2(acc[i], hp.y, wp.y);
            }
        }

        #pragma unroll
        for (int i = 0; i < 4; i++) {
            const int row = 4 * i + rh;
            const float x = sum2(acc[i]);
            const float e = __expf(2.f * x);
            const float h = 1.f - __fdividef(2.f, e + 1.f);
            xw[row * XS + jj] = h;
            g_Hp[((size_t)t * BATCH + b0 + row) * NH + jj] = split_bf(h);
        }
        __syncthreads();
    }
}

// ---------------------------------------------------------------------------
// Kernel 4: projection via mma.sync (HMMA) split-bf16, 3 passes, K in 2 halves.
// C[204800,512] = Hsplit @ Wcsplit^T + bc. CTA 128x128, 8 warps, SMEM 64KB
// per stage -> 2 CTAs/SM.
// ---------------------------------------------------------------------------
#define PJ_A_HI 0
#define PJ_A_LO 16384
#define PJ_B_HI 32768
#define PJ_B_LO 49152
#define PJ_SMEM 65536

__device__ __forceinline__ void ldsm4(u32* r, u32 addr) {
    asm volatile("ldmatrix.sync.aligned.m8n8.x4.shared.b16 {%0,%1,%2,%3}, [%4];"
        : "=r"(r[0]), "=r"(r[1]), "=r"(r[2]), "=r"(r[3]) : "r"(addr));
}
__device__ __forceinline__ void mma16816(float* c, const u32* a, const u32* b) {
    asm volatile(
        "mma.sync.aligned.m16n8k16.row.col.f32.bf16.bf16.f32 "
        "{%0,%1,%2,%3}, {%4,%5,%6,%7}, {%8,%9}, {%0,%1,%2,%3};"
        : "+f"(c[0]), "+f"(c[1]), "+f"(c[2]), "+f"(c[3])
        : "r"(a[0]), "r"(a[1]), "r"(a[2]), "r"(a[3]), "r"(b[0]), "r"(b[1]));
}

__global__ void __launch_bounds__(256, 2) k_proj(float* __restrict__ out) {
    extern __shared__ char smc[];
    const u32 sb = smem_u32(smc);
    const int tid = threadIdx.x;
    const int w = tid >> 5, lane = tid & 31;
    const int col0 = blockIdx.x * 128;
    const int row0 = blockIdx.y * 128;

    const int wm = w & 1, wn = w >> 1;
    const int mbase = wm * 64, nbase = wn * 32;
    const int arow_l = lane & 15, asel = lane >> 4;
    const int brow_l = ((lane >> 4) << 3) + (lane & 7), bsel = (lane >> 3) & 1;

    float acc[4][4][4];
    #pragma unroll
    for (int mt = 0; mt < 4; mt++)
        #pragma unroll
        for (int nt = 0; nt < 4; nt++)
            #pragma unroll
            for (int i = 0; i < 4; i++) acc[mt][nt][i] = 0.f;

    const uint4* Ag = (const uint4*)(g_Hp + (size_t)row0 * NH);
    const uint4* Bg = (const uint4*)(g_Wcp + (size_t)col0 * NH);

    #pragma unroll 1
    for (int half = 0; half < 2; half++) {
        if (half) __syncthreads();   // half-0 ldsm complete before overwrite
        for (int idx = tid; idx < 128 * 16; idx += 256) {
            const int row = idx >> 4, c4 = idx & 15;
            const u32 o = (u32)row * 128 + ((u32)(((c4 >> 1) ^ (row & 7)) << 4)) + (c4 & 1) * 8;
            {
                const uint4 v = Ag[row * 32 + half * 16 + c4];
                uint2 hi, lo;
                hi.x = (v.x & 0xffffu) | (v.y << 16);
                hi.y = (v.z & 0xffffu) | (v.w << 16);
                lo.x = (v.x >> 16) | (v.y & 0xffff0000u);
                lo.y = (v.z >> 16) | (v.w & 0xffff0000u);
                *(uint2*)(smc + PJ_A_HI + o) = hi;
                *(uint2*)(smc + PJ_A_LO + o) = lo;
            }
            {
                const uint4 v = Bg[row * 32 + half * 16 + c4];
                uint2 hi, lo;
                hi.x = (v.x & 0xffffu) | (v.y << 16);
                hi.y = (v.z & 0xffffu) | (v.w << 16);
                lo.x = (v.x >> 16) | (v.y & 0xffff0000u);
                lo.y = (v.z >> 16) | (v.w & 0xffff0000u);
                *(uint2*)(smc + PJ_B_HI + o) = hi;
                *(uint2*)(smc + PJ_B_LO + o) = lo;
            }
        }
        __syncthreads();

        #pragma unroll
        for (int kk = 0; kk < 4; kk++) {
            u32 ahi[4][4], alo[4][4];
            #pragma unroll
            for (int mt = 0; mt < 4; mt++) {
                const int row = mbase + mt * 16 + arow_l;
                const u32 off = (u32)row * 128 + ((u32)(((2 * kk + asel) ^ (row & 7)) << 4));
                ldsm4(ahi[mt], sb + PJ_A_HI + off);
                ldsm4(alo[mt], sb + PJ_A_LO + off);
            }
            u32 bhi[2][4], blo[2][4];
            #pragma unroll
            for (int np = 0; np < 2; np++) {
                const int row = nbase + np * 16 + brow_l;
                const u32 off = (u32)row * 128 + ((u32)(((2 * kk + bsel) ^ (row & 7)) << 4));
                ldsm4(bhi[np], sb + PJ_B_HI + off);
                ldsm4(blo[np], sb + PJ_B_LO + off);
            }
            #pragma unroll
            for (int mt = 0; mt < 4; mt++) {
                #pragma unroll
                for (int nt = 0; nt < 4; nt++) {
                    const u32* bh = &bhi[nt >> 1][(nt & 1) * 2];
                    const u32* bl = &blo[nt >> 1][(nt & 1) * 2];
                    mma16816(acc[mt][nt], ahi[mt], bh);   // hi*hi
                    mma16816(acc[mt][nt], alo[mt], bh);   // lo*hi
                    mma16816(acc[mt][nt], ahi[mt], bl);   // hi*lo
                }
            }
        }
    }

    // Epilogue: C-fragment layout -> direct float2 stores + bias
    const int tq = lane >> 2, tr = lane & 3;
    #pragma unroll
    for (int nt = 0; nt < 4; nt++) {
        const int ncol = col0 + nbase + nt * 8 + tr * 2;
        const float2 bias = *(const float2*)(g_bc + ncol);
        #pragma unroll
        for (int mt = 0; mt < 4; mt++) {
            const int mrow = row0 + mbase + mt * 16 + tq;
            float2 v0, v1;
            v0.x = acc[mt][nt][0] + bias.x; v0.y = acc[mt][nt][1] + bias.y;
            v1.x = acc[mt][nt][2] + bias.x; v1.y = acc[mt][nt][3] + bias.y;
            *(float2*)(out + (size_t)mrow * NSP + ncol) = v0;
            *(float2*)(out + (size_t)(mrow + 8) * NSP + ncol) = v1;
        }
    }
}

// ---------------------------------------------------------------------------
extern "C" void kernel_launch(void* const* d_in, const int* in_sizes, int n_in,
                              void* d_out, int out_size) {
    const float* vel   = (const float*)d_in[0];
    const float* ssp0  = (const float*)d_in[1];
    const float* ie    = (const float*)d_in[2];
    const float* he    = (const float*)d_in[3];
    const float* me    = (const float*)d_in[4];
    const float* ik    = (const float*)d_in[5];
    const float* hk    = (const float*)d_in[6];
    const float* mk    = (const float*)d_in[7];
    const float* AT    = (const float*)d_in[8];
    const float* BT    = (const float*)d_in[9];
    const float* w_c   = (const float*)d_in[10];
    const float* w_h   = (const float*)d_in[11];
    const float* W_lin = (const float*)d_in[12];
    const float* b_lin = (const float*)d_in[13];
    const float* W_ssp = (const float*)d_in[14];
    const float* b_ssp = (const float*)d_in[15];
    float* out = (float*)d_out;

    const int recur_smem = (17408 + 4736 + 3200 + 128 + 128 + 64) * 4;
    cudaFuncSetAttribute(k_recur, cudaFuncAttributeMaxDynamicSharedMemorySize, recur_smem);
    cudaFuncSetAttribute(k_proj,  cudaFuncAttributeMaxDynamicSharedMemorySize, PJ_SMEM);

    k_setup<<<128, 128>>>(ssp0, w_c, w_h);
    k_combine<<<128, 128>>>(W_lin, b_lin, W_ssp, b_ssp);
    k_recur<<<128, 512, recur_smem>>>(vel, ie, he, me, ik, hk, mk, AT, BT);
    dim3 g(4, 1600);
    k_proj<<<g, 256, PJ_SMEM>>>(out);
}

// round 7
// speedup vs baseline: 1.5009x; 1.5009x over previous
#include <cuda_runtime.h>
#include <cuda_bf16.h>

#define T_STEPS 100
#define BATCH   2048
#define NH      128
#define NORD    6
#define NSP     512

typedef unsigned long long ull;
typedef unsigned int u32;

// Scratch (device globals — no allocations allowed)
__device__ __align__(16) __nv_bfloat162 g_Hp[(size_t)T_STEPS * BATCH * NH]; // (hi,lo) per h elem
__device__ __align__(16) float g_h0[BATCH * NH];
__device__ __align__(16) float g_m0[BATCH * NORD];
__device__ __align__(16) __nv_bfloat162 g_Wcp[NSP * NH];                    // combined W, (hi,lo)
__device__ __align__(16) float g_bc[NSP];
// Fused step weights W3 [136 out cols][144 k], split bf16 planes (rows 134-135 & k>=136 zero)
__device__ __align__(16) __nv_bfloat16 g_W3h[136 * 144];
__device__ __align__(16) __nv_bfloat16 g_W3l[136 * 144];

__device__ __forceinline__ u32 smem_u32(const void* p) {
    u32 a;
    asm("{ .reg .u64 t; cvta.to.shared.u64 t, %1; cvt.u32.u64 %0, t; }" : "=r"(a) : "l"(p));
    return a;
}
__device__ __forceinline__ __nv_bfloat162 split_bf(float x) {
    __nv_bfloat16 hi = __float2bfloat16(x);
    __nv_bfloat16 lo = __float2bfloat16(x - __bfloat162float(hi));
    __nv_bfloat162 r; r.x = hi; r.y = lo; return r;
}
__device__ __forceinline__ u32 us(__nv_bfloat16 b) {
    return (u32)__bfloat16_as_ushort(b);
}
__device__ __forceinline__ void ldsm4(u32* r, u32 addr) {
    asm volatile("ldmatrix.sync.aligned.m8n8.x4.shared.b16 {%0,%1,%2,%3}, [%4];"
        : "=r"(r[0]), "=r"(r[1]), "=r"(r[2]), "=r"(r[3]) : "r"(addr));
}
__device__ __forceinline__ void mma16816(float* c, const u32* a, const u32* b) {
    asm volatile(
        "mma.sync.aligned.m16n8k16.row.col.f32.bf16.bf16.f32 "
        "{%0,%1,%2,%3}, {%4,%5,%6,%7}, {%8,%9}, {%0,%1,%2,%3};"
        : "+f"(c[0]), "+f"(c[1]), "+f"(c[2]), "+f"(c[3])
        : "r"(a[0]), "r"(a[1]), "r"(a[2]), "r"(a[3]), "r"(b[0]), "r"(b[1]));
}

// ---------------------------------------------------------------------------
// Kernel 1: initial states  m0 = ssp @ w_c^T,  h0 = ssp @ w_h^T
// ---------------------------------------------------------------------------
__global__ void k_setup(const float* __restrict__ ssp,
                        const float* __restrict__ w_c,
                        const float* __restrict__ w_h) {
    __shared__ float s[16 * 512];
    const int tid = threadIdx.x;
    const int b0 = blockIdx.x * 16;
    for (int i = tid; i < 16 * 512; i += 128) s[i] = ssp[(size_t)b0 * 512 + i];
    __syncthreads();
    {
        float acc[16];
        #pragma unroll
        for (int r = 0; r < 16; r++) acc[r] = 0.f;
        const float* wr = w_h + tid * 512;
        for (int k = 0; k < 512; k += 4) {
            const float4 w4 = *(const float4*)(wr + k);
            #pragma unroll
            for (int r = 0; r < 16; r++) {
                const float4 x4 = *(const float4*)(s + r * 512 + k);
                acc[r] += x4.x * w4.x + x4.y * w4.y + x4.z * w4.z + x4.w * w4.w;
            }
        }
        #pragma unroll
        for (int r = 0; r < 16; r++) g_h0[(size_t)(b0 + r) * NH + tid] = acc[r];
    }
    if (tid < 96) {
        const int o = tid >> 4, r = tid & 15;
        const float* wc = w_c + o * 512;
        float a = 0.f;
        for (int k = 0; k < 512; k++) a += s[r * 512 + k] * wc[k];
        g_m0[(size_t)(b0 + r) * NORD + o] = a;
    }
}

// ---------------------------------------------------------------------------
// Kernel 2: combined weights  Wc = W_ssp @ W_lin (stored split-bf16), bc
// ---------------------------------------------------------------------------
__global__ void k_combine(const float* __restrict__ W_lin,
                          const float* __restrict__ b_lin,
                          const float* __restrict__ W_ssp,
                          const float* __restrict__ b_ssp) {
    __shared__ float s[4 * 512];
    const int tid = threadIdx.x;
    const int i0 = blockIdx.x * 4;
    for (int i = tid; i < 4 * 512; i += 128) s[i] = W_ssp[(size_t)i0 * 512 + i];
    __syncthreads();

    float acc[4] = {0.f, 0.f, 0.f, 0.f};
    for (int j = 0; j < 512; j++) {
        const float wl = W_lin[j * 128 + tid];
        #pragma unroll
        for (int r = 0; r < 4; r++) acc[r] += s[r * 512 + j] * wl;
    }
    #pragma unroll
    for (int r = 0; r < 4; r++) g_Wcp[(size_t)(i0 + r) * NH + tid] = split_bf(acc[r]);

    if (tid < 4) {
        float a = b_ssp[i0 + tid];
        for (int j = 0; j < 512; j++) a += s[tid * 512 + j] * b_lin[j];
        g_bc[i0 + tid] = a;
    }
}

// ---------------------------------------------------------------------------
// Kernel 2b: fused step weights W3 [134 used cols][136 used k].
//   pre_h(j<128):  [HK_j + mkbt_j*he | MK@Ad (j,:) + mkbt_j*me | IK_j + mkbt_j*ie]
//   m'(o):         [BT_o*he          | Ad(o,:) + BT_o*me       | BT_o*ie]
// where mkbt = MK@BT, Ad = I + AT. Stored split-bf16.
// ---------------------------------------------------------------------------
__global__ void k_w3(const float* __restrict__ he, const float* __restrict__ me,
                     const float* __restrict__ ie, const float* __restrict__ ik,
                     const float* __restrict__ hk, const float* __restrict__ mk,
                     const float* __restrict__ AT, const float* __restrict__ BT) {
    const int j = threadIdx.x;
    if (j >= 136) return;
    auto store = [&](int k, float v) {
        __nv_bfloat162 p = split_bf(v);
        g_W3h[j * 144 + k] = p.x;
        g_W3l[j * 144 + k] = p.y;
    };
    if (j < 128) {
        float mkbt = 0.f;
        #pragma unroll
        for (int o = 0; o < 6; o++) mkbt += mk[j * 6 + o] * BT[o];
        for (int k = 0; k < 128; k++) store(k, hk[j * 128 + k] + mkbt * he[k]);
        #pragma unroll
        for (int p = 0; p < 6; p++) {
            float s = mkbt * me[p];
            #pragma unroll
            for (int o = 0; o < 6; o++)
                s += mk[j * 6 + o] * ((o == p ? 1.f : 0.f) + AT[o * 6 + p]);
            store(128 + p, s);
        }
        store(134, ik[j * 2 + 0] + mkbt * ie[0]);
        store(135, ik[j * 2 + 1] + mkbt * ie[1]);
    } else if (j < 134) {
        const int o = j - 128;
        const float bt = BT[o];
        for (int k = 0; k < 128; k++) store(k, bt * he[k]);
        #pragma unroll
        for (int p = 0; p < 6; p++)
            store(128 + p, (o == p ? 1.f : 0.f) + AT[o * 6 + p] + bt * me[p]);
        store(134, bt * ie[0]);
        store(135, bt * ie[1]);
    } else {
        for (int k = 0; k < 136; k++) store(k, 0.f);
    }
    for (int k = 136; k < 144; k++) store(k, 0.f);
}

// ---------------------------------------------------------------------------
// Kernel 3: recurrence v4 — tensor-core step.
// 128 CTAs x 544 threads (17 warps), 16 batch rows/CTA.
// Per step: [16 x 144] @ W3^T -> [16 x 136] via 3-pass split-bf16 mma.sync.
// x = [h(128), m(6), v(2), pad] split into hi/lo bf16 planes, double-buffered.
// Warp w owns output cols 8w..8w+7 (w=16: m cols + v-writer lanes).
// Plane layout: 16 rows x 304B stride (19x16B -> conflict-free ldsm phases).
// One __syncthreads per step.
// ---------------------------------------------------------------------------
__global__ void __launch_bounds__(544) k_recur(const float* __restrict__ vel) {
    __shared__ __align__(16) unsigned char s_xb[19456]; // 2 bufs x 2 planes x 16 x 304B
    __shared__ float s_v[3200];                         // [100][16][2]
    const int tid = threadIdx.x;
    const int b0 = blockIdx.x * 16;
    const u32 xb = smem_u32(s_xb);

    // zero x buffers (incl. all pads)
    for (int i = tid; i < 19456 / 4; i += 544) ((u32*)s_xb)[i] = 0;
    for (int i = tid; i < 3200; i += 544)
        s_v[i] = vel[(size_t)(i >> 5) * (BATCH * 2) + b0 * 2 + (i & 31)];
    __syncthreads();

    // x(0): h0 | m0 | v(0) into buf 0 (hi plane at 0, lo plane at 4864)
    for (int i = tid; i < 2048; i += 544) {
        const int r = i >> 7, c = i & 127;
        const __nv_bfloat162 p = split_bf(g_h0[(size_t)(b0 + r) * NH + c]);
        *(__nv_bfloat16*)(s_xb + r * 304 + c * 2) = p.x;
        *(__nv_bfloat16*)(s_xb + 4864 + r * 304 + c * 2) = p.y;
    }
    for (int i = tid; i < 96; i += 544) {
        const int r = i / 6, o = i % 6;
        const __nv_bfloat162 p = split_bf(g_m0[(size_t)(b0 + r) * NORD + o]);
        *(__nv_bfloat16*)(s_xb + r * 304 + (128 + o) * 2) = p.x;
        *(__nv_bfloat16*)(s_xb + 4864 + r * 304 + (128 + o) * 2) = p.y;
    }
    for (int i = tid; i < 32; i += 544) {
        const int r = i >> 1, c = i & 1;
        const __nv_bfloat162 p = split_bf(s_v[r * 2 + c]);
        *(__nv_bfloat16*)(s_xb + r * 304 + (134 + c) * 2) = p.x;
        *(__nv_bfloat16*)(s_xb + 4864 + r * 304 + (134 + c) * 2) = p.y;
    }

    // B fragments (resident in registers for all 100 steps)
    const int lane = tid & 31, w = tid >> 5;
    const int colB = 8 * w + (lane >> 2);
    u32 bh[9][2], bl[9][2];
    #pragma unroll
    for (int ks = 0; ks < 9; ks++) {
        #pragma unroll
        for (int rr = 0; rr < 2; rr++) {
            const int k0 = ks * 16 + 2 * (lane & 3) + rr * 8;
            bh[ks][rr] = *(const u32*)(g_W3h + colB * 144 + k0);
            bl[ks][rr] = *(const u32*)(g_W3l + colB * 144 + k0);
        }
    }
    __syncthreads();

    const int r0 = lane >> 2;                 // rows r0, r0+8
    const int c0 = 8 * w + 2 * (lane & 3);    // output cols c0, c0+1
    const u32 a_off = (u32)((lane & 15) * 304 + (lane >> 4) * 16);

    #pragma unroll 1
    for (int t = 0; t < T_STEPS; t++) {
        const u32 xro = (u32)(t & 1) * 9728;
        const u32 xwo = xro ^ 9728;
        float acc[4] = {0.f, 0.f, 0.f, 0.f};

        #pragma unroll
        for (int ks = 0; ks < 9; ks++) {
            u32 ah[4], al[4];
            ldsm4(ah, xb + xro + a_off + ks * 32);
            ldsm4(al, xb + xro + 4864 + a_off + ks * 32);
            mma16816(acc, ah, bh[ks]);   // hi*hi
            mma16816(acc, al, bh[ks]);   // lo*hi
            mma16816(acc, ah, bl[ks]);   // hi*lo
        }

        if (c0 < 128) {
            float hv[4];
            #pragma unroll
            for (int i = 0; i < 4; i++) {
                const float e = __expf(2.f * acc[i]);
                hv[i] = 1.f - __fdividef(2.f, e + 1.f);
            }
            const __nv_bfloat162 s00 = split_bf(hv[0]), s01 = split_bf(hv[1]);
            const __nv_bfloat162 s10 = split_bf(hv[2]), s11 = split_bf(hv[3]);
            *(u32*)(s_xb + xwo + r0 * 304 + c0 * 2)        = us(s00.x) | (us(s01.x) << 16);
            *(u32*)(s_xb + xwo + 4864 + r0 * 304 + c0 * 2) = us(s00.y) | (us(s01.y) << 16);
            *(u32*)(s_xb + xwo + (r0 + 8) * 304 + c0 * 2)        = us(s10.x) | (us(s11.x) << 16);
            *(u32*)(s_xb + xwo + 4864 + (r0 + 8) * 304 + c0 * 2) = us(s10.y) | (us(s11.y) << 16);
            uint2 o0, o1;
            o0.x = us(s00.x) | (us(s00.y) << 16); o0.y = us(s01.x) | (us(s01.y) << 16);
            o1.x = us(s10.x) | (us(s10.y) << 16); o1.y = us(s11.x) | (us(s11.y) << 16);
            *(uint2*)(g_Hp + ((size_t)t * BATCH + b0 + r0) * NH + c0) = o0;
            *(uint2*)(g_Hp + ((size_t)t * BATCH + b0 + r0 + 8) * NH + c0) = o1;
        } else if (c0 < 134) {
            const __nv_bfloat162 s00 = split_bf(acc[0]), s01 = split_bf(acc[1]);
            const __nv_bfloat162 s10 = split_bf(acc[2]), s11 = split_bf(acc[3]);
            *(u32*)(s_xb + xwo + r0 * 304 + c0 * 2)        = us(s00.x) | (us(s01.x) << 16);
            *(u32*)(s_xb + xwo + 4864 + r0 * 304 + c0 * 2) = us(s00.y) | (us(s01.y) << 16);
            *(u32*)(s_xb + xwo + (r0 + 8) * 304 + c0 * 2)        = us(s10.x) | (us(s11.x) << 16);
            *(u32*)(s_xb + xwo + 4864 + (r0 + 8) * 304 + c0 * 2) = us(s10.y) | (us(s11.y) << 16);
        } else if (t < T_STEPS - 1) {
            // c0 == 134: stage v(t+1) for rows r0, r0+8
            const __nv_bfloat162 a0 = split_bf(s_v[(t + 1) * 32 + r0 * 2]);
            const __nv_bfloat162 a1 = split_bf(s_v[(t + 1) * 32 + r0 * 2 + 1]);
            const __nv_bfloat162 b0s = split_bf(s_v[(t + 1) * 32 + (r0 + 8) * 2]);
            const __nv_bfloat162 b1s = split_bf(s_v[(t + 1) * 32 + (r0 + 8) * 2 + 1]);
            *(u32*)(s_xb + xwo + r0 * 304 + 268)        = us(a0.x) | (us(a1.x) << 16);
            *(u32*)(s_xb + xwo + 4864 + r0 * 304 + 268) = us(a0.y) | (us(a1.y) << 16);
            *(u32*)(s_xb + xwo + (r0 + 8) * 304 + 268)        = us(b0s.x) | (us(b1s.x) << 16);
            *(u32*)(s_xb + xwo + 4864 + (r0 + 8) * 304 + 268) = us(b0s.y) | (us(b1s.y) << 16);
        }
        __syncthreads();
    }
}

// ---------------------------------------------------------------------------
// Kernel 4: projection via mma.sync (HMMA) split-bf16, 3 passes, K in 2 halves.
// (unchanged from R5: 262 us, tensor 51%)
// ---------------------------------------------------------------------------
#define PJ_A_HI 0
#define PJ_A_LO 16384
#define PJ_B_HI 32768
#define PJ_B_LO 49152
#define PJ_SMEM 65536

__global__ void __launch_bounds__(256, 2) k_proj(float* __restrict__ out) {
    extern __shared__ char smc[];
    const u32 sb = smem_u32(smc);
    const int tid = threadIdx.x;
    const int w = tid >> 5, lane = tid & 31;
    const int col0 = blockIdx.x * 128;
    const int row0 = blockIdx.y * 128;

    const int wm = w & 1, wn = w >> 1;
    const int mbase = wm * 64, nbase = wn * 32;
    const int arow_l = lane & 15, asel = lane >> 4;
    const int brow_l = ((lane >> 4) << 3) + (lane & 7), bsel = (lane >> 3) & 1;

    float acc[4][4][4];
    #pragma unroll
    for (int mt = 0; mt < 4; mt++)
        #pragma unroll
        for (int nt = 0; nt < 4; nt++)
            #pragma unroll
            for (int i = 0; i < 4; i++) acc[mt][nt][i] = 0.f;

    const uint4* Ag = (const uint4*)(g_Hp + (size_t)row0 * NH);
    const uint4* Bg = (const uint4*)(g_Wcp + (size_t)col0 * NH);

    #pragma unroll 1
    for (int half = 0; half < 2; half++) {
        if (half) __syncthreads();
        for (int idx = tid; idx < 128 * 16; idx += 256) {
            const int row = idx >> 4, c4 = idx & 15;
            const u32 o = (u32)row * 128 + ((u32)(((c4 >> 1) ^ (row & 7)) << 4)) + (c4 & 1) * 8;
            {
                const uint4 v = Ag[row * 32 + half * 16 + c4];
                uint2 hi, lo;
                hi.x = (v.x & 0xffffu) | (v.y << 16);
                hi.y = (v.z & 0xffffu) | (v.w << 16);
                lo.x = (v.x >> 16) | (v.y & 0xffff0000u);
                lo.y = (v.z >> 16) | (v.w & 0xffff0000u);
                *(uint2*)(smc + PJ_A_HI + o) = hi;
                *(uint2*)(smc + PJ_A_LO + o) = lo;
            }
            {
                const uint4 v = Bg[row * 32 + half * 16 + c4];
                uint2 hi, lo;
                hi.x = (v.x & 0xffffu) | (v.y << 16);
                hi.y = (v.z & 0xffffu) | (v.w << 16);
                lo.x = (v.x >> 16) | (v.y & 0xffff0000u);
                lo.y = (v.z >> 16) | (v.w & 0xffff0000u);
                *(uint2*)(smc + PJ_B_HI + o) = hi;
                *(uint2*)(smc + PJ_B_LO + o) = lo;
            }
        }
        __syncthreads();

        #pragma unroll
        for (int kk = 0; kk < 4; kk++) {
            u32 ahi[4][4], alo[4][4];
            #pragma unroll
            for (int mt = 0; mt < 4; mt++) {
                const int row = mbase + mt * 16 + arow_l;
                const u32 off = (u32)row * 128 + ((u32)(((2 * kk + asel) ^ (row & 7)) << 4));
                ldsm4(ahi[mt], sb + PJ_A_HI + off);
                ldsm4(alo[mt], sb + PJ_A_LO + off);
            }
            u32 bhi[2][4], blo[2][4];
            #pragma unroll
            for (int np = 0; np < 2; np++) {
                const int row = nbase + np * 16 + brow_l;
                const u32 off = (u32)row * 128 + ((u32)(((2 * kk + bsel) ^ (row & 7)) << 4));
                ldsm4(bhi[np], sb + PJ_B_HI + off);
                ldsm4(blo[np], sb + PJ_B_LO + off);
            }
            #pragma unroll
            for (int mt = 0; mt < 4; mt++) {
                #pragma unroll
                for (int nt = 0; nt < 4; nt++) {
                    const u32* bh = &bhi[nt >> 1][(nt & 1) * 2];
                    const u32* bl = &blo[nt >> 1][(nt & 1) * 2];
                    mma16816(acc[mt][nt], ahi[mt], bh);
                    mma16816(acc[mt][nt], alo[mt], bh);
                    mma16816(acc[mt][nt], ahi[mt], bl);
                }
            }
        }
    }

    const int tq = lane >> 2, tr = lane & 3;
    #pragma unroll
    for (int nt = 0; nt < 4; nt++) {
        const int ncol = col0 + nbase + nt * 8 + tr * 2;
        const float2 bias = *(const float2*)(g_bc + ncol);
        #pragma unroll
        for (int mt = 0; mt < 4; mt++) {
            const int mrow = row0 + mbase + mt * 16 + tq;
            float2 v0, v1;
            v0.x = acc[mt][nt][0] + bias.x; v0.y = acc[mt][nt][1] + bias.y;
            v1.x = acc[mt][nt][2] + bias.x; v1.y = acc[mt][nt][3] + bias.y;
            *(float2*)(out + (size_t)mrow * NSP + ncol) = v0;
            *(float2*)(out + (size_t)(mrow + 8) * NSP + ncol) = v1;
        }
    }
}

// ---------------------------------------------------------------------------
extern "C" void kernel_launch(void* const* d_in, const int* in_sizes, int n_in,
                              void* d_out, int out_size) {
    const float* vel   = (const float*)d_in[0];
    const float* ssp0  = (const float*)d_in[1];
    const float* ie    = (const float*)d_in[2];
    const float* he    = (const float*)d_in[3];
    const float* me    = (const float*)d_in[4];
    const float* ik    = (const float*)d_in[5];
    const float* hk    = (const float*)d_in[6];
    const float* mk    = (const float*)d_in[7];
    const float* AT    = (const float*)d_in[8];
    const float* BT    = (const float*)d_in[9];
    const float* w_c   = (const float*)d_in[10];
    const float* w_h   = (const float*)d_in[11];
    const float* W_lin = (const float*)d_in[12];
    const float* b_lin = (const float*)d_in[13];
    const float* W_ssp = (const float*)d_in[14];
    const float* b_ssp = (const float*)d_in[15];
    float* out = (float*)d_out;

    cudaFuncSetAttribute(k_proj, cudaFuncAttributeMaxDynamicSharedMemorySize, PJ_SMEM);

    k_setup<<<128, 128>>>(ssp0, w_c, w_h);
    k_combine<<<128, 128>>>(W_lin, b_lin, W_ssp, b_ssp);
    k_w3<<<1, 256>>>(he, me, ie, ik, hk, mk, AT, BT);
    k_recur<<<128, 544>>>(vel);
    dim3 g(4, 1600);
    k_proj<<<g, 256, PJ_SMEM>>>(out);
}

// round 8
// speedup vs baseline: 1.9678x; 1.3111x over previous
#include <cuda_runtime.h>
#include <cuda_bf16.h>

#define T_STEPS 100
#define BATCH   2048
#define NH      128
#define NORD    6
#define NSP     512

typedef unsigned long long ull;
typedef unsigned int u32;

// Scratch (device globals — no allocations allowed). Split bf16 planes.
__device__ __align__(16) __nv_bfloat16 g_Hh[(size_t)T_STEPS * BATCH * NH];
__device__ __align__(16) __nv_bfloat16 g_Hl[(size_t)T_STEPS * BATCH * NH];
__device__ __align__(16) float g_h0[BATCH * NH];
__device__ __align__(16) float g_m0[BATCH * NORD];
__device__ __align__(16) __nv_bfloat16 g_Wch[NSP * NH];
__device__ __align__(16) __nv_bfloat16 g_Wcl[NSP * NH];
__device__ __align__(16) float g_bc[NSP];
// Fused step weights W3 [136 out cols][144 k], split bf16 planes
__device__ __align__(16) __nv_bfloat16 g_W3h[136 * 144];
__device__ __align__(16) __nv_bfloat16 g_W3l[136 * 144];

__device__ __forceinline__ u32 smem_u32(const void* p) {
    u32 a;
    asm("{ .reg .u64 t; cvta.to.shared.u64 t, %1; cvt.u32.u64 %0, t; }" : "=r"(a) : "l"(p));
    return a;
}
__device__ __forceinline__ __nv_bfloat162 split_bf(float x) {
    __nv_bfloat16 hi = __float2bfloat16(x);
    __nv_bfloat16 lo = __float2bfloat16(x - __bfloat162float(hi));
    __nv_bfloat162 r; r.x = hi; r.y = lo; return r;
}
__device__ __forceinline__ u32 us(__nv_bfloat16 b) {
    return (u32)__bfloat16_as_ushort(b);
}
__device__ __forceinline__ void ldsm4(u32* r, u32 addr) {
    asm volatile("ldmatrix.sync.aligned.m8n8.x4.shared.b16 {%0,%1,%2,%3}, [%4];"
        : "=r"(r[0]), "=r"(r[1]), "=r"(r[2]), "=r"(r[3]) : "r"(addr));
}
__device__ __forceinline__ void mma16816(float* c, const u32* a, const u32* b) {
    asm volatile(
        "mma.sync.aligned.m16n8k16.row.col.f32.bf16.bf16.f32 "
        "{%0,%1,%2,%3}, {%4,%5,%6,%7}, {%8,%9}, {%0,%1,%2,%3};"
        : "+f"(c[0]), "+f"(c[1]), "+f"(c[2]), "+f"(c[3])
        : "r"(a[0]), "r"(a[1]), "r"(a[2]), "r"(a[3]), "r"(b[0]), "r"(b[1]));
}
__device__ __forceinline__ void cp16(u32 s, const void* g) {
    asm volatile("cp.async.cg.shared.global [%0], [%1], 16;" :: "r"(s), "l"(g));
}

// ---------------------------------------------------------------------------
// Kernel 1 (merged init): grid 513.
//   blocks [0,256):   m0/h0 setup, 8 batch rows per CTA
//   blocks [256,512): Wc = W_ssp @ W_lin (split planes) + bc, 2 rows per CTA
//   block  512:       fused step weights W3
// ---------------------------------------------------------------------------
__global__ void __launch_bounds__(128) k_init(
    const float* __restrict__ ssp,   const float* __restrict__ w_c,
    const float* __restrict__ w_h,   const float* __restrict__ W_lin,
    const float* __restrict__ b_lin, const float* __restrict__ W_ssp,
    const float* __restrict__ b_ssp, const float* __restrict__ he,
    const float* __restrict__ me,    const float* __restrict__ ie,
    const float* __restrict__ ik,    const float* __restrict__ hk,
    const float* __restrict__ mk,    const float* __restrict__ AT,
    const float* __restrict__ BT) {
    __shared__ float s[8 * 512];
    const int tid = threadIdx.x;
    const int bid = blockIdx.x;

    if (bid < 256) {
        // ---- setup: h0, m0 for 8 batch rows ----
        const int b0 = bid * 8;
        for (int i = tid; i < 8 * 512; i += 128) s[i] = ssp[(size_t)b0 * 512 + i];
        __syncthreads();
        float acc[8];
        #pragma unroll
        for (int r = 0; r < 8; r++) acc[r] = 0.f;
        const float* wr = w_h + tid * 512;
        for (int k = 0; k < 512; k += 4) {
            const float4 w4 = *(const float4*)(wr + k);
            #pragma unroll
            for (int r = 0; r < 8; r++) {
                const float4 x4 = *(const float4*)(s + r * 512 + k);
                acc[r] += x4.x * w4.x + x4.y * w4.y + x4.z * w4.z + x4.w * w4.w;
            }
        }
        #pragma unroll
        for (int r = 0; r < 8; r++) g_h0[(size_t)(b0 + r) * NH + tid] = acc[r];
        if (tid < 48) {
            const int o = tid >> 3, r = tid & 7;
            const float* wc = w_c + o * 512;
            float a = 0.f;
            for (int k = 0; k < 512; k++) a += s[r * 512 + k] * wc[k];
            g_m0[(size_t)(b0 + r) * NORD + o] = a;
        }
    } else if (bid < 512) {
        // ---- combine: 2 output rows of Wc ----
        const int i0 = (bid - 256) * 2;
        for (int i = tid; i < 2 * 512; i += 128) s[i] = W_ssp[(size_t)i0 * 512 + i];
        __syncthreads();
        float acc[2] = {0.f, 0.f};
        for (int j = 0; j < 512; j++) {
            const float wl = W_lin[j * 128 + tid];
            acc[0] += s[j] * wl;
            acc[1] += s[512 + j] * wl;
        }
        #pragma unroll
        for (int r = 0; r < 2; r++) {
            const __nv_bfloat162 p = split_bf(acc[r]);
            g_Wch[(size_t)(i0 + r) * NH + tid] = p.x;
            g_Wcl[(size_t)(i0 + r) * NH + tid] = p.y;
        }
        if (tid < 2) {
            float a = b_ssp[i0 + tid];
            for (int j = 0; j < 512; j++) a += s[tid * 512 + j] * b_lin[j];
            g_bc[i0 + tid] = a;
        }
    } else {
        // ---- W3: fused step weights ----
        for (int j = tid; j < 136; j += 128) {
            if (j < 128) {
                float mkbt = 0.f;
                #pragma unroll
                for (int o = 0; o < 6; o++) mkbt += mk[j * 6 + o] * BT[o];
                for (int k = 0; k < 128; k++) {
                    const __nv_bfloat162 p = split_bf(hk[j * 128 + k] + mkbt * he[k]);
                    g_W3h[j * 144 + k] = p.x; g_W3l[j * 144 + k] = p.y;
                }
                #pragma unroll
                for (int p = 0; p < 6; p++) {
                    float sv = mkbt * me[p];
                    #pragma unroll
                    for (int o = 0; o < 6; o++)
                        sv += mk[j * 6 + o] * ((o == p ? 1.f : 0.f) + AT[o * 6 + p]);
                    const __nv_bfloat162 q = split_bf(sv);
                    g_W3h[j * 144 + 128 + p] = q.x; g_W3l[j * 144 + 128 + p] = q.y;
                }
                const __nv_bfloat162 q0 = split_bf(ik[j * 2 + 0] + mkbt * ie[0]);
                const __nv_bfloat162 q1 = split_bf(ik[j * 2 + 1] + mkbt * ie[1]);
                g_W3h[j * 144 + 134] = q0.x; g_W3l[j * 144 + 134] = q0.y;
                g_W3h[j * 144 + 135] = q1.x; g_W3l[j * 144 + 135] = q1.y;
            } else {
                const int o = j - 128;
                const float bt = BT[o];
                for (int k = 0; k < 128; k++) {
                    const __nv_bfloat162 p = split_bf(bt * he[k]);
                    g_W3h[j * 144 + k] = p.x; g_W3l[j * 144 + k] = p.y;
                }
                #pragma unroll
                for (int p = 0; p < 6; p++) {
                    const __nv_bfloat162 q =
                        split_bf((o == p ? 1.f : 0.f) + AT[o * 6 + p] + bt * me[p]);
                    g_W3h[j * 144 + 128 + p] = q.x; g_W3l[j * 144 + 128 + p] = q.y;
                }
                const __nv_bfloat162 q0 = split_bf(bt * ie[0]);
                const __nv_bfloat162 q1 = split_bf(bt * ie[1]);
                g_W3h[j * 144 + 134] = q0.x; g_W3l[j * 144 + 134] = q0.y;
                g_W3h[j * 144 + 135] = q1.x; g_W3l[j * 144 + 135] = q1.y;
            }
            for (int k = 136; k < 144; k++) {
                g_W3h[j * 144 + k] = __float2bfloat16(0.f);
                g_W3l[j * 144 + k] = __float2bfloat16(0.f);
            }
        }
        // zero the pad cols 136..143 rows? rows only go to 135; nothing else.
    }
}

// ---------------------------------------------------------------------------
// Kernel 2: recurrence — tensor-core step (as R7) + dual acc chains + plane out
// ---------------------------------------------------------------------------
__global__ void __launch_bounds__(544) k_recur(const float* __restrict__ vel) {
    __shared__ __align__(16) unsigned char s_xb[19456]; // 2 bufs x 2 planes x 16 x 304B
    __shared__ float s_v[3200];                         // [100][16][2]
    const int tid = threadIdx.x;
    const int b0 = blockIdx.x * 16;
    const u32 xb = smem_u32(s_xb);

    for (int i = tid; i < 19456 / 4; i += 544) ((u32*)s_xb)[i] = 0;
    for (int i = tid; i < 3200; i += 544)
        s_v[i] = vel[(size_t)(i >> 5) * (BATCH * 2) + b0 * 2 + (i & 31)];
    __syncthreads();

    for (int i = tid; i < 2048; i += 544) {
        const int r = i >> 7, c = i & 127;
        const __nv_bfloat162 p = split_bf(g_h0[(size_t)(b0 + r) * NH + c]);
        *(__nv_bfloat16*)(s_xb + r * 304 + c * 2) = p.x;
        *(__nv_bfloat16*)(s_xb + 4864 + r * 304 + c * 2) = p.y;
    }
    for (int i = tid; i < 96; i += 544) {
        const int r = i / 6, o = i % 6;
        const __nv_bfloat162 p = split_bf(g_m0[(size_t)(b0 + r) * NORD + o]);
        *(__nv_bfloat16*)(s_xb + r * 304 + (128 + o) * 2) = p.x;
        *(__nv_bfloat16*)(s_xb + 4864 + r * 304 + (128 + o) * 2) = p.y;
    }
    for (int i = tid; i < 32; i += 544) {
        const int r = i >> 1, c = i & 1;
        const __nv_bfloat162 p = split_bf(s_v[r * 2 + c]);
        *(__nv_bfloat16*)(s_xb + r * 304 + (134 + c) * 2) = p.x;
        *(__nv_bfloat16*)(s_xb + 4864 + r * 304 + (134 + c) * 2) = p.y;
    }

    const int lane = tid & 31, w = tid >> 5;
    const int colB = 8 * w + (lane >> 2);
    u32 bh[9][2], bl[9][2];
    #pragma unroll
    for (int ks = 0; ks < 9; ks++) {
        #pragma unroll
        for (int rr = 0; rr < 2; rr++) {
            const int k0 = ks * 16 + 2 * (lane & 3) + rr * 8;
            bh[ks][rr] = *(const u32*)(g_W3h + colB * 144 + k0);
            bl[ks][rr] = *(const u32*)(g_W3l + colB * 144 + k0);
        }
    }
    __syncthreads();

    const int r0 = lane >> 2;
    const int c0 = 8 * w + 2 * (lane & 3);
    const u32 a_off = (u32)((lane & 15) * 304 + (lane >> 4) * 16);

    #pragma unroll 1
    for (int t = 0; t < T_STEPS; t++) {
        const u32 xro = (u32)(t & 1) * 9728;
        const u32 xwo = xro ^ 9728;
        float acc[4] = {0.f, 0.f, 0.f, 0.f};
        float acc2[4] = {0.f, 0.f, 0.f, 0.f};

        #pragma unroll
        for (int ks = 0; ks < 9; ks++) {
            float* a = (ks & 1) ? acc2 : acc;
            u32 ah[4], al[4];
            ldsm4(ah, xb + xro + a_off + ks * 32);
            ldsm4(al, xb + xro + 4864 + a_off + ks * 32);
            mma16816(a, ah, bh[ks]);   // hi*hi
            mma16816(a, al, bh[ks]);   // lo*hi
            mma16816(a, ah, bl[ks]);   // hi*lo
        }
        #pragma unroll
        for (int i = 0; i < 4; i++) acc[i] += acc2[i];

        if (c0 < 128) {
            float hv[4];
            #pragma unroll
            for (int i = 0; i < 4; i++) {
                const float e = __expf(2.f * acc[i]);
                hv[i] = 1.f - __fdividef(2.f, e + 1.f);
            }
            const __nv_bfloat162 s00 = split_bf(hv[0]), s01 = split_bf(hv[1]);
            const __nv_bfloat162 s10 = split_bf(hv[2]), s11 = split_bf(hv[3]);
            const u32 h0h = us(s00.x) | (us(s01.x) << 16);
            const u32 h0l = us(s00.y) | (us(s01.y) << 16);
            const u32 h1h = us(s10.x) | (us(s11.x) << 16);
            const u32 h1l = us(s10.y) | (us(s11.y) << 16);
            *(u32*)(s_xb + xwo + r0 * 304 + c0 * 2)              = h0h;
            *(u32*)(s_xb + xwo + 4864 + r0 * 304 + c0 * 2)       = h0l;
            *(u32*)(s_xb + xwo + (r0 + 8) * 304 + c0 * 2)        = h1h;
            *(u32*)(s_xb + xwo + 4864 + (r0 + 8) * 304 + c0 * 2) = h1l;
            const size_t go = ((size_t)t * BATCH + b0 + r0) * NH + c0;
            *(u32*)(g_Hh + go) = h0h;
            *(u32*)(g_Hl + go) = h0l;
            *(u32*)(g_Hh + go + 8 * NH) = h1h;
            *(u32*)(g_Hl + go + 8 * NH) = h1l;
        } else if (c0 < 134) {
            const __nv_bfloat162 s00 = split_bf(acc[0]), s01 = split_bf(acc[1]);
            const __nv_bfloat162 s10 = split_bf(acc[2]), s11 = split_bf(acc[3]);
            *(u32*)(s_xb + xwo + r0 * 304 + c0 * 2)        = us(s00.x) | (us(s01.x) << 16);
            *(u32*)(s_xb + xwo + 4864 + r0 * 304 + c0 * 2) = us(s00.y) | (us(s01.y) << 16);
            *(u32*)(s_xb + xwo + (r0 + 8) * 304 + c0 * 2)        = us(s10.x) | (us(s11.x) << 16);
            *(u32*)(s_xb + xwo + 4864 + (r0 + 8) * 304 + c0 * 2) = us(s10.y) | (us(s11.y) << 16);
        } else if (t < T_STEPS - 1) {
            const __nv_bfloat162 a0 = split_bf(s_v[(t + 1) * 32 + r0 * 2]);
            const __nv_bfloat162 a1 = split_bf(s_v[(t + 1) * 32 + r0 * 2 + 1]);
            const __nv_bfloat162 b0s = split_bf(s_v[(t + 1) * 32 + (r0 + 8) * 2]);
            const __nv_bfloat162 b1s = split_bf(s_v[(t + 1) * 32 + (r0 + 8) * 2 + 1]);
            *(u32*)(s_xb + xwo + r0 * 304 + 268)        = us(a0.x) | (us(a1.x) << 16);
            *(u32*)(s_xb + xwo + 4864 + r0 * 304 + 268) = us(a0.y) | (us(a1.y) << 16);
            *(u32*)(s_xb + xwo + (r0 + 8) * 304 + 268)        = us(b0s.x) | (us(b1s.x) << 16);
            *(u32*)(s_xb + xwo + 4864 + (r0 + 8) * 304 + 268) = us(b0s.y) | (us(b1s.y) << 16);
        }
        __syncthreads();
    }
}

// ---------------------------------------------------------------------------
// Kernel 3: projection — HMMA split-bf16, cp.async staged from pre-split planes
// C[204800,512] = Hsplit @ Wcsplit^T + bc. CTA 128x128, K in 2 halves, 64KB.
// ---------------------------------------------------------------------------
#define PJ_A_HI 0
#define PJ_A_LO 16384
#define PJ_B_HI 32768
#define PJ_B_LO 49152
#define PJ_SMEM 65536

__global__ void __launch_bounds__(256, 2) k_proj(float* __restrict__ out) {
    extern __shared__ char smc[];
    const u32 sb = smem_u32(smc);
    const int tid = threadIdx.x;
    const int w = tid >> 5, lane = tid & 31;
    const int col0 = blockIdx.x * 128;
    const int row0 = blockIdx.y * 128;

    const int wm = w & 1, wn = w >> 1;
    const int mbase = wm * 64, nbase = wn * 32;
    const int arow_l = lane & 15, asel = lane >> 4;
    const int brow_l = ((lane >> 4) << 3) + (lane & 7), bsel = (lane >> 3) & 1;

    float acc[4][4][4];
    #pragma unroll
    for (int mt = 0; mt < 4; mt++)
        #pragma unroll
        for (int nt = 0; nt < 4; nt++)
            #pragma unroll
            for (int i = 0; i < 4; i++) acc[mt][nt][i] = 0.f;

    #pragma unroll 1
    for (int half = 0; half < 2; half++) {
        if (half) __syncthreads();   // half-0 ldsm complete before overwrite
        #pragma unroll
        for (int idx = tid; idx < 1024; idx += 256) {
            const int row = idx >> 3, c16 = idx & 7;
            const u32 so = (u32)row * 128 + ((u32)((c16 ^ (row & 7)) << 4));
            const size_t ga = (size_t)(row0 + row) * NH + half * 64 + c16 * 8;
            const size_t gb = (size_t)(col0 + row) * NH + half * 64 + c16 * 8;
            cp16(sb + PJ_A_HI + so, g_Hh + ga);
            cp16(sb + PJ_A_LO + so, g_Hl + ga);
            cp16(sb + PJ_B_HI + so, g_Wch + gb);
            cp16(sb + PJ_B_LO + so, g_Wcl + gb);
        }
        asm volatile("cp.async.commit_group;");
        asm volatile("cp.async.wait_group 0;");
        __syncthreads();

        #pragma unroll
        for (int kk = 0; kk < 4; kk++) {
            u32 ahi[4][4], alo[4][4];
            #pragma unroll
            for (int mt = 0; mt < 4; mt++) {
                const int row = mbase + mt * 16 + arow_l;
                const u32 off = (u32)row * 128 + ((u32)(((2 * kk + asel) ^ (row & 7)) << 4));
                ldsm4(ahi[mt], sb + PJ_A_HI + off);
                ldsm4(alo[mt], sb + PJ_A_LO + off);
            }
            u32 bhi[2][4], blo[2][4];
            #pragma unroll
            for (int np = 0; np < 2; np++) {
                const int row = nbase + np * 16 + brow_l;
                const u32 off = (u32)row * 128 + ((u32)(((2 * kk + bsel) ^ (row & 7)) << 4));
                ldsm4(bhi[np], sb + PJ_B_HI + off);
                ldsm4(blo[np], sb + PJ_B_LO + off);
            }
            #pragma unroll
            for (int mt = 0; mt < 4; mt++) {
                #pragma unroll
                for (int nt = 0; nt < 4; nt++) {
                    const u32* bh = &bhi[nt >> 1][(nt & 1) * 2];
                    const u32* bl = &blo[nt >> 1][(nt & 1) * 2];
                    mma16816(acc[mt][nt], ahi[mt], bh);
                    mma16816(acc[mt][nt], alo[mt], bh);
                    mma16816(acc[mt][nt], ahi[mt], bl);
                }
            }
        }
    }

    const int tq = lane >> 2, tr = lane & 3;
    #pragma unroll
    for (int nt = 0; nt < 4; nt++) {
        const int ncol = col0 + nbase + nt * 8 + tr * 2;
        const float2 bias = *(const float2*)(g_bc + ncol);
        #pragma unroll
        for (int mt = 0; mt < 4; mt++) {
            const int mrow = row0 + mbase + mt * 16 + tq;
            float2 v0, v1;
            v0.x = acc[mt][nt][0] + bias.x; v0.y = acc[mt][nt][1] + bias.y;
            v1.x = acc[mt][nt][2] + bias.x; v1.y = acc[mt][nt][3] + bias.y;
            *(float2*)(out + (size_t)mrow * NSP + ncol) = v0;
            *(float2*)(out + (size_t)(mrow + 8) * NSP + ncol) = v1;
        }
    }
}

// ---------------------------------------------------------------------------
extern "C" void kernel_launch(void* const* d_in, const int* in_sizes, int n_in,
                              void* d_out, int out_size) {
    const float* vel   = (const float*)d_in[0];
    const float* ssp0  = (const float*)d_in[1];
    const float* ie    = (const float*)d_in[2];
    const float* he    = (const float*)d_in[3];
    const float* me    = (const float*)d_in[4];
    const float* ik    = (const float*)d_in[5];
    const float* hk    = (const float*)d_in[6];
    const float* mk    = (const float*)d_in[7];
    const float* AT    = (const float*)d_in[8];
    const float* BT    = (const float*)d_in[9];
    const float* w_c   = (const float*)d_in[10];
    const float* w_h   = (const float*)d_in[11];
    const float* W_lin = (const float*)d_in[12];
    const float* b_lin = (const float*)d_in[13];
    const float* W_ssp = (const float*)d_in[14];
    const float* b_ssp = (const float*)d_in[15];
    float* out = (float*)d_out;

    cudaFuncSetAttribute(k_proj, cudaFuncAttributeMaxDynamicSharedMemorySize, PJ_SMEM);

    k_init<<<513, 128>>>(ssp0, w_c, w_h, W_lin, b_lin, W_ssp, b_ssp,
                         he, me, ie, ik, hk, mk, AT, BT);
    k_recur<<<128, 544>>>(vel);
    dim3 g(4, 1600);
    k_proj<<<g, 256, PJ_SMEM>>>(out);
}